// round 16
// baseline (speedup 1.0000x reference)
#include <cuda_runtime.h>
#include <cuda_bf16.h>
#include <math.h>
#include <stdint.h>

// GridGRU: N=32, T=512, D=1024, H=1024
// inputs: x (N,T,D), prev_ht (N,H), weight (2048,6144), bias (6144)
// outputs: h (N,T,D) then last_ht (N,H), concatenated in d_out.

#define NN 32
#define TT 512
#define DD 1024
#define HH 1024
#define MROWS (NN*TT)        // 16384
#define WLD 6144
#define NBS 64               // persistent scan blocks (32 gate + 16 cand cols each)
#define GK2 40               // gemm smem k stride (bf16); 80B rows
#define WST 2056             // scan weight col stride (hi at +0, lo at +1024; pad 8)
#define HS 136               // scan activation smem k stride (272B = 17*16, skew 4)

// ---------------- scratch (device globals) -----------------------------------
__device__ float g_gates[(size_t)MROWS * 3072];        // 192 MB
__device__ float g_hcur[NN * HH];
__device__ float g_U[NN * HH];
__device__ float g_UD[(size_t)MROWS * DD];             // 64 MB
__device__ __nv_bfloat16 g_Wt_hi[(size_t)6144 * 2048]; // transposed [col][k]
__device__ __nv_bfloat16 g_Wt_lo[(size_t)6144 * 2048];
__device__ __nv_bfloat16 g_X_hi[(size_t)MROWS * DD], g_X_lo[(size_t)MROWS * DD];
__device__ __nv_bfloat16 g_HT_hi[(size_t)MROWS * HH], g_HT_lo[(size_t)MROWS * HH];
__device__ __nv_bfloat16 g_RX_hi[(size_t)MROWS * DD], g_RX_lo[(size_t)MROWS * DD];
__device__ __nv_bfloat16 g_h_hi[NN * HH], g_h_lo[NN * HH];
__device__ __nv_bfloat16 g_rh_hi[NN * HH], g_rh_lo[NN * HH];
__device__ unsigned g_barcnt;

__device__ __forceinline__ void mma16816(float* c, const uint32_t* a, const uint32_t* b)
{
    asm volatile(
        "mma.sync.aligned.m16n8k16.row.col.f32.bf16.bf16.f32 "
        "{%0,%1,%2,%3}, {%4,%5,%6,%7}, {%8,%9}, {%0,%1,%2,%3};\n"
        : "+f"(c[0]), "+f"(c[1]), "+f"(c[2]), "+f"(c[3])
        : "r"(a[0]), "r"(a[1]), "r"(a[2]), "r"(a[3]), "r"(b[0]), "r"(b[1]));
}

__device__ __forceinline__ void ldsm_x4(uint32_t* r, uint32_t saddr)
{
    asm volatile("ldmatrix.sync.aligned.m8n8.x4.shared.b16 {%0,%1,%2,%3}, [%4];\n"
                 : "=r"(r[0]), "=r"(r[1]), "=r"(r[2]), "=r"(r[3]) : "r"(saddr));
}

__device__ __forceinline__ void cpa16(void* smem, const void* g)
{
    uint32_t a = (uint32_t)__cvta_generic_to_shared(smem);
    asm volatile("cp.async.cg.shared.global [%0], [%1], 16;" :: "r"(a), "l"(g));
}
#define CPA_COMMIT asm volatile("cp.async.commit_group;" ::: "memory")
#define CPA_WAIT(n) asm volatile("cp.async.wait_group %0;" :: "n"(n) : "memory")

// ---------------- prep: split x to bf16 hi/lo --------------------------------
__global__ void conv_x_kernel(const float* __restrict__ x)
{
    long i = ((long)blockIdx.x * 256 + threadIdx.x) * 8;
    float4 v0 = *(const float4*)(x + i);
    float4 v1 = *(const float4*)(x + i + 4);
    float v[8] = {v0.x, v0.y, v0.z, v0.w, v1.x, v1.y, v1.z, v1.w};
    __align__(16) __nv_bfloat16 hb[8], lb[8];
#pragma unroll
    for (int e = 0; e < 8; e++) {
        __nv_bfloat16 h = __float2bfloat16(v[e]);
        hb[e] = h;
        lb[e] = __float2bfloat16(v[e] - __bfloat162float(h));
    }
    *(uint4*)&g_X_hi[i] = *(uint4*)hb;
    *(uint4*)&g_X_lo[i] = *(uint4*)lb;
}

// ---------------- prep: split + transpose weight to [col][k] bf16 ------------
__global__ void conv_w_kernel(const float* __restrict__ W)
{
    __shared__ float ws[64][65];
    const int k0 = blockIdx.x * 64, c0 = blockIdx.y * 64;
    const int tid = threadIdx.x;
#pragma unroll
    for (int s = 0; s < 4; s++) {
        int f = tid + s * 256;
        int kr = f >> 4, cc = (f & 15) * 4;
        float4 v = *(const float4*)(W + (long)(k0 + kr) * WLD + c0 + cc);
        ws[kr][cc] = v.x; ws[kr][cc + 1] = v.y; ws[kr][cc + 2] = v.z; ws[kr][cc + 3] = v.w;
    }
    __syncthreads();
    const int col = tid & 63, kq = tid >> 6;
    __align__(16) __nv_bfloat16 hb[16], lb[16];
#pragma unroll
    for (int j = 0; j < 16; j++) {
        float v = ws[kq * 16 + j][col];
        __nv_bfloat16 h = __float2bfloat16(v);
        hb[j] = h;
        lb[j] = __float2bfloat16(v - __bfloat162float(h));
    }
    long dst = (long)(c0 + col) * 2048 + k0 + kq * 16;
    ((uint4*)&g_Wt_hi[dst])[0] = ((uint4*)hb)[0];
    ((uint4*)&g_Wt_hi[dst])[1] = ((uint4*)hb)[1];
    ((uint4*)&g_Wt_lo[dst])[0] = ((uint4*)lb)[0];
    ((uint4*)&g_Wt_lo[dst])[1] = ((uint4*)lb)[1];
}

// ---------------- big GEMM: bf16 hi/lo, cp.async + ldmatrix (unchanged) ------
template<int EPI>
__global__ void __launch_bounds__(256, 2)
mma_gemm(const __nv_bfloat16* __restrict__ A0h, const __nv_bfloat16* __restrict__ A0l,
         const __nv_bfloat16* __restrict__ A1h, const __nv_bfloat16* __restrict__ A1l,
         const __nv_bfloat16* __restrict__ Bth, const __nv_bfloat16* __restrict__ Btl,
         const float* __restrict__ bias, const float* __restrict__ X,
         float* __restrict__ out, const float* __restrict__ UD,
         int K, int ldc)
{
    extern __shared__ __align__(16) char gsm[];
    __nv_bfloat16* As = (__nv_bfloat16*)gsm;        // [stage][hi/lo][128*GK2]
    __nv_bfloat16* Bs = As + 2 * 2 * 128 * GK2;
    const uint32_t s0s = (uint32_t)__cvta_generic_to_shared(gsm);
    const uint32_t PLANE = 128 * GK2 * 2;

    const int tid = threadIdx.x, lane = tid & 31, warp = tid >> 5;
    const int warpM = warp & 1, warpN = warp >> 1;
    const int g = lane >> 2, tig = lane & 3;
    const int row0 = blockIdx.y * 128, col0 = blockIdx.x * 128;
    const int rA = warpM * 64, cB = warpN * 32;
    const int r0 = tid >> 2, kq = (tid & 3) * 8;
    const int r1 = r0 + 64;

    const int arow = ((lane >> 3) & 1) * 8 + (lane & 7);
    const int acol = (lane >> 4) * 8;
    const int brow = (lane >> 4) * 8 + (lane & 7);
    const int bcol = ((lane >> 3) & 1) * 8;

    float acc[4][4][4];
#pragma unroll
    for (int i = 0; i < 4; i++)
#pragma unroll
        for (int j = 0; j < 4; j++)
#pragma unroll
            for (int e = 0; e < 4; e++) acc[i][j][e] = 0.f;

    auto ISSUE = [&](int k0, int st) {
        const __nv_bfloat16 *ph, *pl; int kb;
        if (k0 < 1024) { ph = A0h; pl = A0l; kb = k0; }
        else           { ph = A1h; pl = A1l; kb = k0 - 1024; }
        __nv_bfloat16* Ah = As + (st * 2 + 0) * 128 * GK2;
        __nv_bfloat16* Al = As + (st * 2 + 1) * 128 * GK2;
        __nv_bfloat16* Bh = Bs + (st * 2 + 0) * 128 * GK2;
        __nv_bfloat16* Bl = Bs + (st * 2 + 1) * 128 * GK2;
        cpa16(Ah + r0 * GK2 + kq, ph + (long)(row0 + r0) * 1024 + kb + kq);
        cpa16(Ah + r1 * GK2 + kq, ph + (long)(row0 + r1) * 1024 + kb + kq);
        cpa16(Al + r0 * GK2 + kq, pl + (long)(row0 + r0) * 1024 + kb + kq);
        cpa16(Al + r1 * GK2 + kq, pl + (long)(row0 + r1) * 1024 + kb + kq);
        cpa16(Bh + r0 * GK2 + kq, Bth + (long)(col0 + r0) * 2048 + k0 + kq);
        cpa16(Bh + r1 * GK2 + kq, Bth + (long)(col0 + r1) * 2048 + k0 + kq);
        cpa16(Bl + r0 * GK2 + kq, Btl + (long)(col0 + r0) * 2048 + k0 + kq);
        cpa16(Bl + r1 * GK2 + kq, Btl + (long)(col0 + r1) * 2048 + k0 + kq);
    };

    const int KT = K / 32;
    ISSUE(0, 0); CPA_COMMIT;

    for (int kt = 0; kt < KT; kt++) {
        const int st = kt & 1;
        if (kt + 1 < KT) { ISSUE((kt + 1) * 32, st ^ 1); CPA_COMMIT; CPA_WAIT(1); }
        else             { CPA_WAIT(0); }
        __syncthreads();

        const uint32_t sAh = s0s + (st * 2 + 0) * PLANE;
        const uint32_t sAl = s0s + (st * 2 + 1) * PLANE;
        const uint32_t sBh = s0s + 4 * PLANE + (st * 2 + 0) * PLANE;
        const uint32_t sBl = s0s + 4 * PLANE + (st * 2 + 1) * PLANE;

#pragma unroll
        for (int kk = 0; kk < 32; kk += 16) {
            uint32_t ah[4][4], al[4][4], bh[4][2], bl[4][2];
#pragma unroll
            for (int i = 0; i < 4; i++) {
                uint32_t aoff = (uint32_t)(((rA + i * 16 + arow) * GK2 + kk + acol) * 2);
                ldsm_x4(ah[i], sAh + aoff);
                ldsm_x4(al[i], sAl + aoff);
            }
#pragma unroll
            for (int jp = 0; jp < 2; jp++) {
                uint32_t boff = (uint32_t)(((cB + jp * 16 + brow) * GK2 + kk + bcol) * 2);
                uint32_t t[4];
                ldsm_x4(t, sBh + boff);
                bh[jp * 2][0] = t[0]; bh[jp * 2][1] = t[1];
                bh[jp * 2 + 1][0] = t[2]; bh[jp * 2 + 1][1] = t[3];
                ldsm_x4(t, sBl + boff);
                bl[jp * 2][0] = t[0]; bl[jp * 2][1] = t[1];
                bl[jp * 2 + 1][0] = t[2]; bl[jp * 2 + 1][1] = t[3];
            }
#pragma unroll
            for (int i = 0; i < 4; i++)
#pragma unroll
                for (int j = 0; j < 4; j++) {
                    mma16816(acc[i][j], ah[i], bh[j]);
                    mma16816(acc[i][j], ah[i], bl[j]);
                    mma16816(acc[i][j], al[i], bh[j]);
                }
        }
        __syncthreads();
    }

    auto epi2 = [&](long row, int col, float v0, float v1) {
        v0 += bias[col]; v1 += bias[col + 1];
        if (EPI == 0) {
            out[row * (long)ldc + col]     = v0;
            out[row * (long)ldc + col + 1] = v1;
        } else if (EPI == 1) {
            float s0 = 1.f / (1.f + __expf(-v0));
            float s1 = 1.f / (1.f + __expf(-v1));
            if (col < 1024) {
                out[row * 1024 + col]     = s0;
                out[row * 1024 + col + 1] = s1;
            } else {
                int d = col - 1024;
                float rx0 = s0 * X[row * 1024 + d];
                float rx1 = s1 * X[row * 1024 + d + 1];
                __nv_bfloat16 h0 = __float2bfloat16(rx0);
                __nv_bfloat16 h1 = __float2bfloat16(rx1);
                __nv_bfloat162 hp; hp.x = h0; hp.y = h1;
                __nv_bfloat162 lp;
                lp.x = __float2bfloat16(rx0 - __bfloat162float(h0));
                lp.y = __float2bfloat16(rx1 - __bfloat162float(h1));
                *(__nv_bfloat162*)&g_RX_hi[row * 1024 + d] = hp;
                *(__nv_bfloat162*)&g_RX_lo[row * 1024 + d] = lp;
            }
        } else {
            float hc0 = tanhf(v0), hc1 = tanhf(v1);
            float x0 = X[row * 1024 + col], x1 = X[row * 1024 + col + 1];
            out[row * 1024 + col]     = x0 + UD[row * 1024 + col] * (hc0 - x0);
            out[row * 1024 + col + 1] = x1 + UD[row * 1024 + col + 1] * (hc1 - x1);
        }
    };

#pragma unroll
    for (int i = 0; i < 4; i++) {
        long r = row0 + rA + i * 16 + g;
#pragma unroll
        for (int j = 0; j < 4; j++) {
            int cc = col0 + cB + j * 8 + tig * 2;
            epi2(r,     cc, acc[i][j][0], acc[i][j][1]);
            epi2(r + 8, cc, acc[i][j][2], acc[i][j][3]);
        }
    }
}

// ---------------- scan init --------------------------------------------------
__global__ void scan_init(const float* __restrict__ prev_ht)
{
    int i = blockIdx.x * 256 + threadIdx.x;   // 32768
    if (i == 0) g_barcnt = 0;
    float v = prev_ht[i];
    g_hcur[i] = v;
    __nv_bfloat16 hi = __float2bfloat16(v);
    g_h_hi[i] = hi;
    g_h_lo[i] = __float2bfloat16(v - __bfloat162float(hi));
}

__device__ __forceinline__ void gridbar(unsigned target)
{
    __syncthreads();
    if (threadIdx.x == 0) {
        asm volatile("red.release.gpu.global.add.u32 [%0], 1;"
                     :: "l"(&g_barcnt) : "memory");
        unsigned v;
        do {
            asm volatile("ld.acquire.gpu.global.u32 %0, [%1];"
                         : "=r"(v) : "l"(&g_barcnt) : "memory");
        } while (v < target);
    }
    __syncthreads();
}

// ---------------- persistent scan: 64 blocks, halved broadcast traffic -------
// Block bx owns gate cols [bx*32, +32) (bx<32 -> U, else RH) and candidate
// cols [bx*16, +16). Weight slices persist in smem with per-col interleaved
// hi/lo layout: col plane stride WST=2056, hi at +0, lo at +1024.
// Activations staged in 8 chunks of 128k via a 2-buffer cp.async ring (stride
// HS=136, 16B-aligned rows); the reduction buffer OVERLAYS the staging bufs.
extern __shared__ __align__(16) char dsraw[];
__global__ void __launch_bounds__(256, 1)
scan_persistent()
{
    __nv_bfloat16* ws1 = (__nv_bfloat16*)dsraw;       // 32 cols x WST
    __nv_bfloat16* ws2 = ws1 + 32 * WST;              // 16 cols x WST
    __nv_bfloat16* hbuf = ws2 + 16 * WST;             // 2 bufs x [hi|lo] x 32*HS
    float* red = (float*)hbuf;                        // overlay (32768B <= 34816B)

    const int tid = threadIdx.x, bx = blockIdx.x;
    const int lane = tid & 31, warp = tid >> 5;
    const int g = lane >> 2, tig = lane & 3;

    const int gcol0 = bx * 32;       // gate col base (0..2047)
    const int dcol0 = bx * 16;       // candidate col base (0..1023)
    const bool isU = (bx < 32);

    // ---- load weight slices (once): hi at c*WST, lo at c*WST+1024 ----
#pragma unroll
    for (int s = 0; s < 16; s++) {
        int f = tid + s * 256;                 // 0..4095
        int c = f >> 7, q = (f & 127) * 8;
        *(uint4*)(ws1 + c * WST + q)        = *(const uint4*)&g_Wt_hi[(long)(gcol0 + c) * 2048 + 1024 + q];
        *(uint4*)(ws1 + c * WST + 1024 + q) = *(const uint4*)&g_Wt_lo[(long)(gcol0 + c) * 2048 + 1024 + q];
    }
#pragma unroll
    for (int s = 0; s < 8; s++) {
        int f = tid + s * 256;                 // 0..2047
        int c = f >> 7, q = (f & 127) * 8;
        *(uint4*)(ws2 + c * WST + q)        = *(const uint4*)&g_Wt_hi[(long)(2048 + dcol0 + c) * 2048 + 1024 + q];
        *(uint4*)(ws2 + c * WST + 1024 + q) = *(const uint4*)&g_Wt_lo[(long)(2048 + dcol0 + c) * 2048 + 1024 + q];
    }
    __syncthreads();

    // output mapping: phase1 = 32 rows x 32 cols (4/thread); phase2 = 32x16 (2/thread)
    const int row = tid >> 3;        // 0..31
    const int c4  = (tid & 7) * 4;
    const int c2  = (tid & 7) * 2;
    const int gc  = gcol0 + c4;

    // staging map: id = tid + s*256 -> r = id>>4, q = (id&15)*8 (covers 32x128)
    const int sr0 = tid >> 4, sr1 = (tid + 256) >> 4;
    const int sq = (tid & 15) * 8;

    auto BUF = [&](int b, int pl) { return hbuf + (b * 2 + pl) * 32 * HS; };
    auto ISSUE = [&](const __nv_bfloat16* srcH, const __nv_bfloat16* srcL,
                     int ch, int b) {
        __nv_bfloat16* dh = BUF(b, 0);
        __nv_bfloat16* dl = BUF(b, 1);
        int kc = ch * 128;
        cpa16(dh + sr0 * HS + sq, srcH + sr0 * 1024 + kc + sq);
        cpa16(dh + sr1 * HS + sq, srcH + sr1 * 1024 + kc + sq);
        cpa16(dl + sr0 * HS + sq, srcL + sr0 * 1024 + kc + sq);
        cpa16(dl + sr1 * HS + sq, srcL + sr1 * 1024 + kc + sq);
        CPA_COMMIT;
    };

    unsigned tgt = NBS;

    for (int t = 0; t < TT; t++) {
        // ================= phase 1: 32x32 gate GEMM =================
        ISSUE(g_h_hi, g_h_lo, 0, 0);

        float4 gv = *(const float4*)&g_gates[((long)row * TT + t) * 3072 + gc];
        float4 hv = make_float4(0.f, 0.f, 0.f, 0.f);
        if (!isU)
            hv = __ldcg((const float4*)&g_hcur[row * 1024 + (gc - 1024)]);
        float2 gv2 = *(const float2*)&g_gates[((long)row * TT + t) * 3072 + 2048 + dcol0 + c2];
        float2 hp = __ldcg((const float2*)&g_hcur[row * 1024 + dcol0 + c2]);

        float acc[2][4][4];
#pragma unroll
        for (int i = 0; i < 2; i++)
#pragma unroll
            for (int j = 0; j < 4; j++)
#pragma unroll
                for (int e = 0; e < 4; e++) acc[i][j][e] = 0.f;

#pragma unroll
        for (int ch = 0; ch < 8; ch++) {
            if (ch < 7) { ISSUE(g_h_hi, g_h_lo, ch + 1, (ch + 1) & 1); CPA_WAIT(1); }
            else        { CPA_WAIT(0); }
            __syncthreads();
            const __nv_bfloat16* Ah = BUF(ch & 1, 0);
            const __nv_bfloat16* Al = BUF(ch & 1, 1);
            const int kl = warp * 16 + tig * 2;      // warp-exclusive 16k window
            const int kg = ch * 128 + kl;
            uint32_t ah[2][4], al[2][4], bh[4][2], bl[4][2];
#pragma unroll
            for (int i = 0; i < 2; i++) {
                int r = i * 16 + g;
                ah[i][0] = *(const uint32_t*)&Ah[r * HS + kl];
                ah[i][1] = *(const uint32_t*)&Ah[(r + 8) * HS + kl];
                ah[i][2] = *(const uint32_t*)&Ah[r * HS + kl + 8];
                ah[i][3] = *(const uint32_t*)&Ah[(r + 8) * HS + kl + 8];
                al[i][0] = *(const uint32_t*)&Al[r * HS + kl];
                al[i][1] = *(const uint32_t*)&Al[(r + 8) * HS + kl];
                al[i][2] = *(const uint32_t*)&Al[r * HS + kl + 8];
                al[i][3] = *(const uint32_t*)&Al[(r + 8) * HS + kl + 8];
            }
#pragma unroll
            for (int j = 0; j < 4; j++) {
                int n = j * 8 + g;
                bh[j][0] = *(const uint32_t*)&ws1[n * WST + kg];
                bh[j][1] = *(const uint32_t*)&ws1[n * WST + kg + 8];
                bl[j][0] = *(const uint32_t*)&ws1[n * WST + 1024 + kg];
                bl[j][1] = *(const uint32_t*)&ws1[n * WST + 1024 + kg + 8];
            }
#pragma unroll
            for (int i = 0; i < 2; i++)
#pragma unroll
                for (int j = 0; j < 4; j++) {
                    mma16816(acc[i][j], ah[i], bh[j]);
                    mma16816(acc[i][j], ah[i], bl[j]);
                    mma16816(acc[i][j], al[i], bh[j]);
                }
            __syncthreads();    // buffer (ch&1) safe to reissue next iteration
        }

        // ---- reduction overlaid on dead staging buffers ----
#pragma unroll
        for (int i = 0; i < 2; i++)
#pragma unroll
            for (int j = 0; j < 4; j++) {
                int r = i * 16 + g, c = j * 8 + tig * 2;
                red[warp * 1024 + r * 32 + c]           = acc[i][j][0];
                red[warp * 1024 + r * 32 + c + 1]       = acc[i][j][1];
                red[warp * 1024 + (r + 8) * 32 + c]     = acc[i][j][2];
                red[warp * 1024 + (r + 8) * 32 + c + 1] = acc[i][j][3];
            }
        __syncthreads();
        {
            float v0 = gv.x, v1 = gv.y, v2 = gv.z, v3 = gv.w;
#pragma unroll
            for (int w = 0; w < 8; w++) {
                float4 p = *(const float4*)&red[w * 1024 + row * 32 + c4];
                v0 += p.x; v1 += p.y; v2 += p.z; v3 += p.w;
            }
            float s0 = 1.f / (1.f + __expf(-v0));
            float s1 = 1.f / (1.f + __expf(-v1));
            float s2 = 1.f / (1.f + __expf(-v2));
            float s3 = 1.f / (1.f + __expf(-v3));
            if (isU) {
                *(float4*)&g_U[row * 1024 + gc] = make_float4(s0, s1, s2, s3);
            } else {
                int d = gc - 1024;
                float rv[4] = {s0 * hv.x, s1 * hv.y, s2 * hv.z, s3 * hv.w};
                __align__(8) __nv_bfloat16 hb4[4], lb4[4];
#pragma unroll
                for (int e = 0; e < 4; e++) {
                    __nv_bfloat16 h = __float2bfloat16(rv[e]);
                    hb4[e] = h;
                    lb4[e] = __float2bfloat16(rv[e] - __bfloat162float(h));
                }
                *(uint2*)&g_rh_hi[row * 1024 + d] = *(uint2*)hb4;
                *(uint2*)&g_rh_lo[row * 1024 + d] = *(uint2*)lb4;
            }
        }

        gridbar(tgt); tgt += NBS;

        // ================= phase 2: 32x16 candidate GEMM =================
        ISSUE(g_rh_hi, g_rh_lo, 0, 0);
        float2 uu = __ldcg((const float2*)&g_U[row * 1024 + dcol0 + c2]);

        float acc2[2][2][4];
#pragma unroll
        for (int i = 0; i < 2; i++)
#pragma unroll
            for (int j = 0; j < 2; j++)
#pragma unroll
                for (int e = 0; e < 4; e++) acc2[i][j][e] = 0.f;

#pragma unroll
        for (int ch = 0; ch < 8; ch++) {
            if (ch < 7) { ISSUE(g_rh_hi, g_rh_lo, ch + 1, (ch + 1) & 1); CPA_WAIT(1); }
            else        { CPA_WAIT(0); }
            __syncthreads();
            const __nv_bfloat16* Ah = BUF(ch & 1, 0);
            const __nv_bfloat16* Al = BUF(ch & 1, 1);
            const int kl = warp * 16 + tig * 2;
            const int kg = ch * 128 + kl;
            uint32_t ah[2][4], al[2][4], bh[2][2], bl[2][2];
#pragma unroll
            for (int i = 0; i < 2; i++) {
                int r = i * 16 + g;
                ah[i][0] = *(const uint32_t*)&Ah[r * HS + kl];
                ah[i][1] = *(const uint32_t*)&Ah[(r + 8) * HS + kl];
                ah[i][2] = *(const uint32_t*)&Ah[r * HS + kl + 8];
                ah[i][3] = *(const uint32_t*)&Ah[(r + 8) * HS + kl + 8];
                al[i][0] = *(const uint32_t*)&Al[r * HS + kl];
                al[i][1] = *(const uint32_t*)&Al[(r + 8) * HS + kl];
                al[i][2] = *(const uint32_t*)&Al[r * HS + kl + 8];
                al[i][3] = *(const uint32_t*)&Al[(r + 8) * HS + kl + 8];
            }
#pragma unroll
            for (int j = 0; j < 2; j++) {
                int n = j * 8 + g;
                bh[j][0] = *(const uint32_t*)&ws2[n * WST + kg];
                bh[j][1] = *(const uint32_t*)&ws2[n * WST + kg + 8];
                bl[j][0] = *(const uint32_t*)&ws2[n * WST + 1024 + kg];
                bl[j][1] = *(const uint32_t*)&ws2[n * WST + 1024 + kg + 8];
            }
#pragma unroll
            for (int i = 0; i < 2; i++)
#pragma unroll
                for (int j = 0; j < 2; j++) {
                    mma16816(acc2[i][j], ah[i], bh[j]);
                    mma16816(acc2[i][j], ah[i], bl[j]);
                    mma16816(acc2[i][j], al[i], bh[j]);
                }
            __syncthreads();
        }

#pragma unroll
        for (int i = 0; i < 2; i++)
#pragma unroll
            for (int j = 0; j < 2; j++) {
                int r = i * 16 + g, c = j * 8 + tig * 2;
                red[warp * 512 + r * 16 + c]           = acc2[i][j][0];
                red[warp * 512 + r * 16 + c + 1]       = acc2[i][j][1];
                red[warp * 512 + (r + 8) * 16 + c]     = acc2[i][j][2];
                red[warp * 512 + (r + 8) * 16 + c + 1] = acc2[i][j][3];
            }
        __syncthreads();
        {
            float v0 = gv2.x, v1 = gv2.y;
#pragma unroll
            for (int w = 0; w < 8; w++) {
                float2 p = *(const float2*)&red[w * 512 + row * 16 + c2];
                v0 += p.x; v1 += p.y;
            }
            float hc0 = tanhf(v0), hc1 = tanhf(v1);
            float hn0 = hp.x + uu.x * (hc0 - hp.x);
            float hn1 = hp.y + uu.y * (hc1 - hp.y);
            int d = dcol0 + c2;
            *(float2*)&g_hcur[row * 1024 + d] = make_float2(hn0, hn1);
            __nv_bfloat16 h0 = __float2bfloat16(hn0);
            __nv_bfloat16 h1 = __float2bfloat16(hn1);
            __nv_bfloat162 hip; hip.x = h0; hip.y = h1;
            __nv_bfloat162 lop;
            lop.x = __float2bfloat16(hn0 - __bfloat162float(h0));
            lop.y = __float2bfloat16(hn1 - __bfloat162float(h1));
            *(__nv_bfloat162*)&g_h_hi[row * 1024 + d] = hip;
            *(__nv_bfloat162*)&g_h_lo[row * 1024 + d] = lop;
            long ho = ((long)row * TT + t) * 1024 + d;
            *(__nv_bfloat162*)&g_HT_hi[ho] = hip;
            *(__nv_bfloat162*)&g_HT_lo[ho] = lop;
        }

        gridbar(tgt); tgt += NBS;
    }
}

__global__ void copy_last(float* __restrict__ out)
{
    int i = blockIdx.x * 256 + threadIdx.x;   // 32768
    out[i] = g_hcur[i];
}

// ---------------- launch ------------------------------------------------------
#define SCAN_SMEM ((48 * WST + 4 * 32 * HS) * 2)   // 232,192 B
#define GEMM_SMEM 81920

extern "C" void kernel_launch(void* const* d_in, const int* in_sizes, int n_in,
                              void* d_out, int out_size)
{
    const float* x       = (const float*)d_in[0];
    const float* prev_ht = (const float*)d_in[1];
    const float* weight  = (const float*)d_in[2];
    const float* bias    = (const float*)d_in[3];
    float* out = (float*)d_out;

    float *G, *UD;
    __nv_bfloat16 *Wth, *Wtl, *Xh, *Xl, *HTh, *HTl, *RXh, *RXl;
    cudaGetSymbolAddress((void**)&G,   g_gates);
    cudaGetSymbolAddress((void**)&UD,  g_UD);
    cudaGetSymbolAddress((void**)&Wth, g_Wt_hi);
    cudaGetSymbolAddress((void**)&Wtl, g_Wt_lo);
    cudaGetSymbolAddress((void**)&Xh,  g_X_hi);
    cudaGetSymbolAddress((void**)&Xl,  g_X_lo);
    cudaGetSymbolAddress((void**)&HTh, g_HT_hi);
    cudaGetSymbolAddress((void**)&HTl, g_HT_lo);
    cudaGetSymbolAddress((void**)&RXh, g_RX_hi);
    cudaGetSymbolAddress((void**)&RXl, g_RX_lo);

    static int attr_set = 0;
    if (!attr_set) {
        cudaFuncSetAttribute(scan_persistent,
                             cudaFuncAttributeMaxDynamicSharedMemorySize, SCAN_SMEM);
        cudaFuncSetAttribute(mma_gemm<0>,
                             cudaFuncAttributeMaxDynamicSharedMemorySize, GEMM_SMEM);
        cudaFuncSetAttribute(mma_gemm<1>,
                             cudaFuncAttributeMaxDynamicSharedMemorySize, GEMM_SMEM);
        cudaFuncSetAttribute(mma_gemm<2>,
                             cudaFuncAttributeMaxDynamicSharedMemorySize, GEMM_SMEM);
        attr_set = 1;
    }

    // prep: split W (transposed) and x into bf16 hi/lo
    conv_w_kernel<<<dim3(2048 / 64, 6144 / 64), 256>>>(weight);
    conv_x_kernel<<<MROWS * DD / 8 / 256, 256>>>(x);

    // gates = x @ Wxt + bt
    mma_gemm<0><<<dim3(3072 / 128, MROWS / 128), 256, GEMM_SMEM>>>(
        Xh, Xl, Xh, Xl, Wth, Wtl, bias, nullptr, G, nullptr, 1024, 3072);

    // scan
    scan_init<<<128, 256>>>(prev_ht);
    scan_persistent<<<NBS, 256, SCAN_SMEM>>>();

    // F1: sigmoid(bd[:2D] + [x|ht] @ W[:,3072:5120]) -> UD, RX
    mma_gemm<1><<<dim3(2048 / 128, MROWS / 128), 256, GEMM_SMEM>>>(
        Xh, Xl, HTh, HTl, Wth + (size_t)3072 * 2048, Wtl + (size_t)3072 * 2048,
        bias + 3072, x, UD, nullptr, 2048, 2048);

    // F2: tanh(bd[2D:] + [rd*x|ht] @ W[:,5120:6144]); out = x + ud*(hc-x)
    mma_gemm<2><<<dim3(1024 / 128, MROWS / 128), 256, GEMM_SMEM>>>(
        RXh, RXl, HTh, HTl, Wth + (size_t)5120 * 2048, Wtl + (size_t)5120 * 2048,
        bias + 5120, x, out, UD, 2048, 1024);

    // last_ht
    copy_last<<<128, 256>>>(out + (size_t)MROWS * 1024);
}